// round 1
// baseline (speedup 1.0000x reference)
#include <cuda_runtime.h>
#include <cstdint>

#define N_BOX     8192
#define MAX_KEEP  256
#define MIN_SCORE 0.3f
#define NMS_THR   0.3f
#define SORT_THREADS 1024

// ---------------- scratch (no allocation allowed) ----------------
__device__ unsigned long long g_keys[N_BOX];
__device__ int    g_sorted_idx[N_BOX];
__device__ float  g_ss[N_BOX];
__device__ float4 g_bbox[N_BOX];   // x1,y1,x2,y2 (sorted order)
__device__ float  g_area[N_BOX];

// ---------------- kernel 1: pack sort keys ----------------
// ascending sort of key = (~score_bits << 32) | idx
//   => descending score, ties broken by smaller original index (stable argsort(-s))
__global__ void build_keys_kernel(const float* __restrict__ score) {
    int i = blockIdx.x * blockDim.x + threadIdx.x;
    if (i < N_BOX) {
        unsigned int b = __float_as_uint(score[i]);   // scores in [0,1): positive => bits monotone
        g_keys[i] = ((unsigned long long)(~b) << 32) | (unsigned int)i;
    }
}

// ---------------- kernel 2: single-block bitonic sort + gather ----------------
extern __shared__ unsigned long long s_keys[];  // 8192 * 8 = 64 KB dynamic smem

__global__ void __launch_bounds__(SORT_THREADS, 1)
sort_gather_kernel(const float* __restrict__ box) {
    const int tid = threadIdx.x;

    #pragma unroll
    for (int i = tid; i < N_BOX; i += SORT_THREADS) s_keys[i] = g_keys[i];
    __syncthreads();

    for (int k = 2; k <= N_BOX; k <<= 1) {
        for (int j = k >> 1; j > 0; j >>= 1) {
            #pragma unroll
            for (int i = tid; i < N_BOX; i += SORT_THREADS) {
                int ixj = i ^ j;
                if (ixj > i) {
                    unsigned long long a = s_keys[i];
                    unsigned long long b = s_keys[ixj];
                    bool up = ((i & k) == 0);
                    if ((a > b) == up) { s_keys[i] = b; s_keys[ixj] = a; }
                }
            }
            __syncthreads();
        }
    }

    // gather: sorted position p -> original index, score, xyxy bbox, area
    #pragma unroll
    for (int p = tid; p < N_BOX; p += SORT_THREADS) {
        unsigned long long key = s_keys[p];
        int idx = (int)(key & 0xFFFFFFFFull);
        g_sorted_idx[p] = idx;
        float s = __uint_as_float(~(unsigned int)(key >> 32));
        g_ss[p] = s;
        float cx = box[idx * 16 + 0];
        float cy = box[idx * 16 + 1];
        float w  = box[idx * 16 + 2];
        float h  = box[idx * 16 + 3];
        float hw = w * 0.5f, hh = h * 0.5f;
        float x1 = cx - hw, y1 = cy - hh, x2 = cx + hw, y2 = cy + hh;
        g_bbox[p] = make_float4(x1, y1, x2, y2);
        g_area[p] = (x2 - x1) * (y2 - y1);   // match reference (area from rounded xyxy)
    }
}

// ---------------- kernel 3: greedy NMS (<=256 serial steps) + output ----------------
__global__ void __launch_bounds__(1024, 1)
nms_kernel(const float* __restrict__ box, float* __restrict__ out) {
    __shared__ __align__(8) unsigned char removed[N_BOX / 8];  // 1024 bytes; thread t owns byte t
    __shared__ int   kept_list[MAX_KEEP];
    __shared__ float bb_x1, bb_y1, bb_x2, bb_y2, bb_ar;
    __shared__ int   s_next, s_count;

    const int tid = threadIdx.x;

    // each thread holds 8 consecutive sorted boxes in registers
    float x1[8], y1[8], x2[8], y2[8], ar[8];
    unsigned int myrem = 0;
    #pragma unroll
    for (int k = 0; k < 8; k++) {
        int p = tid * 8 + k;
        float4 bb = g_bbox[p];
        x1[k] = bb.x; y1[k] = bb.y; x2[k] = bb.z; y2[k] = bb.w;
        ar[k] = g_area[p];
        if (!(g_ss[p] >= MIN_SCORE)) myrem |= (1u << k);   // invalid: never kept, never suppresses
    }
    removed[tid] = (unsigned char)myrem;
    if (tid == 0) s_count = 0;
    __syncthreads();

    while (true) {
        // warp 0: find first clear bit in removed bitmap (lowest surviving candidate)
        if (tid < 32) {
            const unsigned long long* w = (const unsigned long long*)removed;
            int local = N_BOX;
            #pragma unroll
            for (int q = 3; q >= 0; q--) {
                unsigned long long cand = ~w[tid * 4 + q];
                if (cand) local = (tid * 4 + q) * 64 + (__ffsll((long long)cand) - 1);
            }
            #pragma unroll
            for (int off = 16; off; off >>= 1)
                local = min(local, __shfl_down_sync(0xFFFFFFFFu, local, off));
            if (tid == 0) s_next = local;
        }
        __syncthreads();

        int ni  = s_next;
        int cnt = s_count;
        if (ni >= N_BOX || cnt >= MAX_KEEP) break;

        if (tid == 0) {
            float4 bb = g_bbox[ni];
            bb_x1 = bb.x; bb_y1 = bb.y; bb_x2 = bb.z; bb_y2 = bb.w;
            bb_ar = g_area[ni];
            kept_list[cnt] = ni;
            s_count = cnt + 1;
        }
        __syncthreads();

        float X1 = bb_x1, Y1 = bb_y1, X2 = bb_x2, Y2 = bb_y2, AR = bb_ar;
        unsigned int m = 0;
        #pragma unroll
        for (int k = 0; k < 8; k++) {
            float lx = fmaxf(X1, x1[k]);
            float ly = fmaxf(Y1, y1[k]);
            float rx = fminf(X2, x2[k]);
            float ry = fminf(Y2, y2[k]);
            float iw = fmaxf(rx - lx, 0.0f);
            float ih = fmaxf(ry - ly, 0.0f);
            float inter = iw * ih;
            float iou = inter / (AR + ar[k] - inter + 1e-9f);
            if (iou > NMS_THR) m |= (1u << k);
        }
        myrem |= m;
        // guarantee the kept box itself is retired even if degenerate (area ~ 0 => self-IoU ~ 0)
        if ((ni >> 3) == tid) myrem |= (1u << (ni & 7));
        removed[tid] = (unsigned char)myrem;
        __syncthreads();
    }

    // ---------------- write outputs ----------------
    // layout: [0,256) score | [256,4352) box (256x16) | [4352,4608) valid (1.0/0.0)
    int cnt = s_count;
    for (int k = tid; k < MAX_KEEP; k += blockDim.x) {
        if (k < cnt) {
            out[k]        = g_ss[kept_list[k]];
            out[4352 + k] = 1.0f;
        } else {
            out[k]        = 0.0f;
            out[4352 + k] = 0.0f;
        }
    }
    for (int e = tid; e < MAX_KEEP * 16; e += blockDim.x) {
        int k = e >> 4, c = e & 15;
        float v = 0.0f;
        if (k < cnt) {
            int orig = g_sorted_idx[kept_list[k]];
            v = box[orig * 16 + c];
        }
        out[256 + e] = v;
    }
}

// ---------------- launch ----------------
extern "C" void kernel_launch(void* const* d_in, const int* in_sizes, int n_in,
                              void* d_out, int out_size) {
    const float* score = (const float*)d_in[0];
    const float* box   = (const float*)d_in[1];
    float* out = (float*)d_out;

    cudaFuncSetAttribute(sort_gather_kernel,
                         cudaFuncAttributeMaxDynamicSharedMemorySize,
                         N_BOX * (int)sizeof(unsigned long long));

    build_keys_kernel<<<(N_BOX + 255) / 256, 256>>>(score);
    sort_gather_kernel<<<1, SORT_THREADS, N_BOX * sizeof(unsigned long long)>>>(box);
    nms_kernel<<<1, 1024>>>(box, out);
}

// round 2
// speedup vs baseline: 1.4908x; 1.4908x over previous
#include <cuda_runtime.h>
#include <cstdint>

#define N_BOX     8192
#define MAX_KEEP  256
#define MIN_SCORE 0.3f
#define NMS_THR   0.3f
#define NT        1024
#define BPT       (N_BOX / NT)   // 8 boxes per thread

extern __shared__ unsigned char dynsmem[];

__global__ void __launch_bounds__(NT, 1)
nms_fused_kernel(const float* __restrict__ score,
                 const float* __restrict__ box,
                 float* __restrict__ out) {
    // dynamic smem layout: [0,128K) bbox float4 (x1,y1,x2,y2); [128K,160K) score bits
    float4*       s_bbox  = (float4*)dynsmem;
    unsigned int* s_score = (unsigned int*)(dynsmem + N_BOX * sizeof(float4));

    __shared__ unsigned int s_wsc[NT / 32];
    __shared__ int          s_wp[NT / 32];
    __shared__ int          s_sel;
    __shared__ float        s_selsc;
    __shared__ int          kept_idx[MAX_KEEP];
    __shared__ float        kept_sc[MAX_KEEP];

    const int tid  = threadIdx.x;
    const int wid  = tid >> 5;
    const int lane = tid & 31;

    // ---------------- prologue: boxes -> shared ----------------
    for (int i = tid; i < N_BOX; i += NT) {
        s_score[i] = __float_as_uint(score[i]);
        float4 b = *(const float4*)(box + i * 16);   // cx,cy,w,h (row is 64B-aligned)
        float hw = b.z * 0.5f, hh = b.w * 0.5f;
        s_bbox[i] = make_float4(b.x - hw, b.y - hh, b.x + hw, b.y + hh);
    }
    __syncthreads();

    // per-thread alive bitmask over its 8 boxes (invalid = score < 0.3 -> dead)
    unsigned int alive = 0;
    const int base = tid * BPT;
    #pragma unroll
    for (int k = 0; k < BPT; k++)
        if (__uint_as_float(s_score[base + k]) >= MIN_SCORE) alive |= (1u << k);

    // ---------------- fused select-max + suppress loop ----------------
    int kept = 0;
    while (true) {
        // 1) local argmax over alive boxes (ascending k => min-index tie-break)
        unsigned int best = 0; int bp = 0x7FFFFFFF;
        unsigned int m = alive;
        while (m) {
            int k = __ffs(m) - 1; m &= m - 1;
            unsigned int sc = s_score[base + k];
            if (sc > best) { best = sc; bp = base + k; }
        }
        // 2) warp argmax: max score bits, then min index among winners
        unsigned int wmax = __reduce_max_sync(0xFFFFFFFFu, best);
        int cand = (best == wmax) ? bp : 0x7FFFFFFF;
        int wpos = __reduce_min_sync(0xFFFFFFFFu, cand);
        if (lane == 0) { s_wsc[wid] = wmax; s_wp[wid] = wpos; }
        __syncthreads();
        // 3) cross-warp argmax in warp 0 (exactly 32 warps)
        if (wid == 0) {
            unsigned int v = s_wsc[lane];
            int p = s_wp[lane];
            unsigned int gm = __reduce_max_sync(0xFFFFFFFFu, v);
            int c2 = (v == gm) ? p : 0x7FFFFFFF;
            int gp = __reduce_min_sync(0xFFFFFFFFu, c2);
            if (lane == 0) {
                s_sel   = (gm == 0) ? -1 : gp;    // 0 sentinel: valid scores >= 0.3 have bits > 0
                s_selsc = __uint_as_float(gm);
            }
        }
        __syncthreads();

        int sel = s_sel;
        if (sel < 0 || kept >= MAX_KEEP) break;
        if (tid == 0) { kept_idx[kept] = sel; kept_sc[kept] = s_selsc; }
        kept++;   // uniform across threads

        // 4) suppress: IoU vs selected, only over alive bits
        float4 B  = s_bbox[sel];
        float  AR = (B.z - B.x) * (B.w - B.y);
        m = alive;
        while (m) {
            int k = __ffs(m) - 1; m &= m - 1;
            int p = base + k;
            float4 b = s_bbox[p];
            float lx = fmaxf(B.x, b.x);
            float ly = fmaxf(B.y, b.y);
            float rx = fminf(B.z, b.z);
            float ry = fminf(B.w, b.w);
            float iw = fmaxf(rx - lx, 0.0f);
            float ih = fmaxf(ry - ly, 0.0f);
            float inter = iw * ih;
            float arb = (b.z - b.x) * (b.w - b.y);
            float iou = inter / (AR + arb - inter + 1e-9f);   // exact division, matches reference
            if (iou > NMS_THR || p == sel) alive &= ~(1u << k);
        }
    }

    // ---------------- outputs ----------------
    // layout: [0,256) score | [256,4352) box (256x16) | [4352,4608) valid (1.0/0.0)
    for (int k = tid; k < MAX_KEEP; k += NT) {
        bool v = k < kept;
        out[k]        = v ? kept_sc[k] : 0.0f;
        out[4352 + k] = v ? 1.0f : 0.0f;
    }
    for (int e = tid; e < MAX_KEEP * 16; e += NT) {
        int k = e >> 4, c = e & 15;
        out[256 + e] = (k < kept) ? box[kept_idx[k] * 16 + c] : 0.0f;
    }
}

// ---------------- launch ----------------
extern "C" void kernel_launch(void* const* d_in, const int* in_sizes, int n_in,
                              void* d_out, int out_size) {
    const float* score = (const float*)d_in[0];
    const float* box   = (const float*)d_in[1];
    float* out = (float*)d_out;

    const int dyn = N_BOX * (int)sizeof(float4) + N_BOX * (int)sizeof(unsigned int); // 160 KB
    cudaFuncSetAttribute(nms_fused_kernel,
                         cudaFuncAttributeMaxDynamicSharedMemorySize, dyn);

    nms_fused_kernel<<<1, NT, dyn>>>(score, box, out);
}

// round 3
// speedup vs baseline: 5.7880x; 3.8824x over previous
#include <cuda_runtime.h>
#include <cstdint>

#define N_BOX     8192
#define MAX_KEEP  256
#define MIN_SCORE 0.3f
#define NMS_THR   0.3f
#define NT        1024
#define NBKT      4096
#define FULL      0xFFFFFFFFu

extern __shared__ unsigned char dynsmem[];

__global__ void __launch_bounds__(NT, 1)
detect_kernel(const float* __restrict__ score,
              const float* __restrict__ box,
              float* __restrict__ out)
{
    // dynamic smem: [0,64K) sorted u64 keys; [64K,80K) histogram; [80K,96K) offsets
    unsigned long long* s_key = (unsigned long long*)dynsmem;
    unsigned int*       s_cnt = (unsigned int*)(dynsmem + 65536);
    unsigned int*       s_off = (unsigned int*)(dynsmem + 81920);

    __shared__ float kx1[MAX_KEEP], ky1[MAX_KEEP], kx2[MAX_KEEP], ky2[MAX_KEEP], kar[MAX_KEEP];
    __shared__ float kept_sc[MAX_KEEP];
    __shared__ int   kept_id[MAX_KEEP];
    __shared__ float4 s_cb[32];
    __shared__ float  s_car[32];
    __shared__ unsigned int  s_row[32];
    __shared__ unsigned char s_sup[32];
    __shared__ unsigned int  s_wsum[32];
    __shared__ int s_nvalid, s_kc, s_kbase;
    __shared__ unsigned int s_keep;

    const int tid  = threadIdx.x;
    const int lane = tid & 31;
    const int wid  = tid >> 5;

    // ---------------- phase 1: bucket sort (descending score, stable) ----------------
    for (int i = tid; i < NBKT; i += NT) s_cnt[i] = 0;
    if (tid == 0) s_kc = 0;
    __syncthreads();

    float sc[8]; int bk[8];
    #pragma unroll
    for (int k = 0; k < 8; k++) {
        int i = tid + k * NT;
        float s = score[i];
        sc[k] = s;
        int b = -1;
        if (s >= MIN_SCORE) {
            b = 4095 - min(4095, (int)(s * 4096.0f));   // monotone: score desc -> bucket asc
            atomicAdd(&s_cnt[b], 1u);
        }
        bk[k] = b;
    }
    __syncthreads();

    // exclusive scan of 4096 counters (1024 threads x 4)
    unsigned int c0 = s_cnt[tid*4+0], c1 = s_cnt[tid*4+1], c2 = s_cnt[tid*4+2], c3 = s_cnt[tid*4+3];
    unsigned int tsum = c0 + c1 + c2 + c3;
    unsigned int p = tsum;
    #pragma unroll
    for (int d = 1; d < 32; d <<= 1) {
        unsigned int v = __shfl_up_sync(FULL, p, d);
        if (lane >= d) p += v;
    }
    if (lane == 31) s_wsum[wid] = p;
    __syncthreads();
    if (wid == 0) {
        unsigned int w = s_wsum[lane];
        unsigned int q = w;
        #pragma unroll
        for (int d = 1; d < 32; d <<= 1) {
            unsigned int v = __shfl_up_sync(FULL, q, d);
            if (lane >= d) q += v;
        }
        s_wsum[lane] = q - w;                    // exclusive warp offset
        if (lane == 31) s_nvalid = (int)q;       // total valid
    }
    __syncthreads();
    unsigned int base = s_wsum[wid] + (p - tsum);
    s_off[tid*4+0] = base;
    s_off[tid*4+1] = base + c0;
    s_off[tid*4+2] = base + c0 + c1;
    s_off[tid*4+3] = base + c0 + c1 + c2;
    __syncthreads();

    // scatter (afterwards s_off[b] = start of bucket b+1)
    #pragma unroll
    for (int k = 0; k < 8; k++) {
        if (bk[k] >= 0) {
            int i = tid + k * NT;
            unsigned int pos = atomicAdd(&s_off[bk[k]], 1u);
            s_key[pos] = ((unsigned long long)(~__float_as_uint(sc[k])) << 32) | (unsigned int)i;
        }
    }
    __syncthreads();

    // intra-bucket insertion sort on full u64 key (exact total order, handles ties)
    for (int b = tid; b < NBKT; b += NT) {
        int lo = b ? (int)s_off[b-1] : 0;
        int hi = (int)s_off[b];
        for (int i = lo + 1; i < hi; i++) {
            unsigned long long v = s_key[i];
            int j = i - 1;
            while (j >= lo && s_key[j] > v) { s_key[j+1] = s_key[j]; j--; }
            s_key[j+1] = v;
        }
    }
    __syncthreads();

    const int nval = s_nvalid;

    // ---------------- phase 2: batched greedy NMS ----------------
    int kc = 0;
    for (int cb = 0; cb < nval && kc < MAX_KEEP; cb += 32) {
        const int nb = min(32, nval - cb);

        // stage candidate bboxes (warp 0)
        if (wid == 0 && lane < nb) {
            unsigned long long key = s_key[cb + lane];
            int idx = (int)(key & 0xFFFFFFFFull);
            float4 b4 = *(const float4*)(box + idx * 16);
            float hw = b4.z * 0.5f, hh = b4.w * 0.5f;
            float4 bb = make_float4(b4.x - hw, b4.y - hh, b4.x + hw, b4.y + hh);
            s_cb[lane]  = bb;
            s_car[lane] = (bb.z - bb.x) * (bb.w - bb.y);
        }
        __syncthreads();

        // fused: intra-batch IoU row + suppressed-by-kept check (warp w <-> candidate w)
        if (wid < nb) {
            float4 B  = s_cb[wid];
            float  AR = s_car[wid];
            // row w of 32x32 matrix
            bool hit = false;
            if (lane < nb) {
                float4 b = s_cb[lane];
                float lx = fmaxf(B.x, b.x), ly = fmaxf(B.y, b.y);
                float rx = fminf(B.z, b.z), ry = fminf(B.w, b.w);
                float iw = fmaxf(rx - lx, 0.0f), ih = fmaxf(ry - ly, 0.0f);
                float inter = iw * ih;
                hit = inter / (AR + s_car[lane] - inter + 1e-9f) > NMS_THR;
            }
            unsigned int row = __ballot_sync(FULL, hit);
            if (lane == 0) s_row[wid] = row;

            // check vs kept list, 32 at a time, early exit
            bool sup = false;
            for (int kb = lane; ; kb += 32) {
                bool h = false;
                if (kb < kc) {
                    float lx = fmaxf(B.x, kx1[kb]), ly = fmaxf(B.y, ky1[kb]);
                    float rx = fminf(B.z, kx2[kb]), ry = fminf(B.w, ky2[kb]);
                    float iw = fmaxf(rx - lx, 0.0f), ih = fmaxf(ry - ly, 0.0f);
                    float inter = iw * ih;
                    h = inter / (AR + kar[kb] - inter + 1e-9f) > NMS_THR;
                }
                if (__ballot_sync(FULL, h)) { sup = true; break; }
                if (kb - lane + 32 >= kc) break;
            }
            if (lane == 0) s_sup[wid] = (unsigned char)sup;
        }
        __syncthreads();

        // warp 0: serial resolve (lane 0) + parallel append
        if (wid == 0) {
            if (lane == 0) {
                unsigned int alive = (nb == 32) ? FULL : ((1u << nb) - 1u);
                for (int t = 0; t < nb; t++)
                    if (s_sup[t]) alive &= ~(1u << t);
                unsigned int keep = 0;
                int k2 = kc;
                while (alive && k2 < MAX_KEEP) {
                    int t = __ffs(alive) - 1;
                    keep |= 1u << t;
                    k2++;
                    alive &= ~s_row[t];
                    alive &= ~(1u << t);
                }
                s_keep = keep; s_kbase = kc; s_kc = k2;
            }
            __syncwarp(FULL);
            unsigned int keep = s_keep;
            int kb0 = s_kbase;
            if (keep & (1u << lane)) {
                int pos = kb0 + __popc(keep & ((1u << lane) - 1u));
                float4 bb = s_cb[lane];
                kx1[pos] = bb.x; ky1[pos] = bb.y; kx2[pos] = bb.z; ky2[pos] = bb.w;
                kar[pos] = s_car[lane];
                unsigned long long key = s_key[cb + lane];
                kept_id[pos] = (int)(key & 0xFFFFFFFFull);
                kept_sc[pos] = __uint_as_float(~(unsigned int)(key >> 32));
            }
        }
        __syncthreads();
        kc = s_kc;
    }

    // ---------------- outputs ----------------
    // layout: [0,256) score | [256,4352) box (256x16) | [4352,4608) valid
    for (int k = tid; k < MAX_KEEP; k += NT) {
        bool v = k < kc;
        out[k]        = v ? kept_sc[k] : 0.0f;
        out[4352 + k] = v ? 1.0f : 0.0f;
    }
    for (int e = tid; e < MAX_KEEP * 16; e += NT) {
        int k = e >> 4, c = e & 15;
        out[256 + e] = (k < kc) ? box[kept_id[k] * 16 + c] : 0.0f;
    }
}

// ---------------- launch ----------------
extern "C" void kernel_launch(void* const* d_in, const int* in_sizes, int n_in,
                              void* d_out, int out_size) {
    const float* score = (const float*)d_in[0];
    const float* box   = (const float*)d_in[1];
    float* out = (float*)d_out;

    const int dyn = 98304;  // 64K keys + 16K hist + 16K offsets
    cudaFuncSetAttribute(detect_kernel,
                         cudaFuncAttributeMaxDynamicSharedMemorySize, dyn);
    detect_kernel<<<1, NT, dyn>>>(score, box, out);
}